// round 5
// baseline (speedup 1.0000x reference)
#include <cuda_runtime.h>
#include <math.h>

// ---------------- problem constants ----------------
#define S_   8192
#define H_   16
#define D_   128
#define HD_  2048
#define C_   12
#define MP_  12
#define CTX_ 24
#define POS_ 13
#define NBLK_ 683          // ceil(8192/12)

// scratch (device globals: allocation-free rule)
__device__ float g_q[(size_t)S_ * HD_];
__device__ float g_k[(size_t)S_ * HD_];
__device__ float g_v[(size_t)S_ * HD_];
__device__ float g_ctx[(size_t)S_ * HD_];
__device__ float g_relk[(size_t)POS_ * HD_];

// ---------------- SGEMM: C[M,N] = A[M,K] @ B[K,N], row-major fp32 ----------------
// 128x128 tile, BK=8, 256 threads, 8x8 per thread.
__global__ __launch_bounds__(256, 2)
void sgemm128(const float* __restrict__ A, const float* __restrict__ B,
              float* __restrict__ Cmat, int M, int N, int K)
{
    __shared__ __align__(16) float As[8][128];
    __shared__ __align__(16) float Bs[8][128];

    const int tid  = threadIdx.x;
    const int brow = blockIdx.y * 128;
    const int bcol = blockIdx.x * 128;
    const int tx = (tid & 15) * 8;      // col offset within tile
    const int ty = (tid >> 4) * 8;      // row offset within tile

    const int arow = tid >> 1;          // 0..127
    const int acol = (tid & 1) * 4;     // 0 or 4
    const int bkr  = tid >> 5;          // 0..7
    const int bc4  = (tid & 31) * 4;    // 0..124

    const float* Ap = A + (size_t)(brow + arow) * K + acol;
    const float* Bp = B + (size_t)bkr * N + bcol + bc4;
    const bool aval = (brow + arow) < M;

    float acc[8][8];
#pragma unroll
    for (int i = 0; i < 8; i++)
#pragma unroll
        for (int j = 0; j < 8; j++) acc[i][j] = 0.f;

    for (int kt = 0; kt < K; kt += 8) {
        float4 av = aval ? *(const float4*)(Ap + kt) : make_float4(0.f, 0.f, 0.f, 0.f);
        float4 bv = *(const float4*)(Bp + (size_t)kt * N);

        __syncthreads();
        As[acol + 0][arow] = av.x;
        As[acol + 1][arow] = av.y;
        As[acol + 2][arow] = av.z;
        As[acol + 3][arow] = av.w;
        *(float4*)&Bs[bkr][bc4] = bv;
        __syncthreads();

#pragma unroll
        for (int kk = 0; kk < 8; kk++) {
            float4 a0 = *(const float4*)&As[kk][ty];
            float4 a1 = *(const float4*)&As[kk][ty + 4];
            float4 b0 = *(const float4*)&Bs[kk][tx];
            float4 b1 = *(const float4*)&Bs[kk][tx + 4];
            float a[8] = {a0.x, a0.y, a0.z, a0.w, a1.x, a1.y, a1.z, a1.w};
            float b[8] = {b0.x, b0.y, b0.z, b0.w, b1.x, b1.y, b1.z, b1.w};
#pragma unroll
            for (int i = 0; i < 8; i++)
#pragma unroll
                for (int j = 0; j < 8; j++) acc[i][j] = fmaf(a[i], b[j], acc[i][j]);
        }
    }

#pragma unroll
    for (int i = 0; i < 8; i++) {
        int row = brow + ty + i;
        if (row < M) {
            float4* cp = (float4*)(Cmat + (size_t)row * N + bcol + tx);
            cp[0] = make_float4(acc[i][0], acc[i][1], acc[i][2], acc[i][3]);
            cp[1] = make_float4(acc[i][4], acc[i][5], acc[i][6], acc[i][7]);
        }
    }
}

// ---------------- chunked attention: one block per (n, h) ----------------
__global__ __launch_bounds__(128)
void attn_kernel(const float* __restrict__ q, const float* __restrict__ k,
                 const float* __restrict__ v, const float* __restrict__ relk,
                 const float* __restrict__ pds, float* __restrict__ ctx)
{
    __shared__ float qs[C_][D_ + 1];
    __shared__ float ks[CTX_][D_ + 1];
    __shared__ float vs[CTX_][D_ + 1];
    __shared__ float rks[POS_][D_ + 1];
    __shared__ float ac[C_][CTX_ + 1];
    __shared__ float bd[C_][POS_ + 1];
    __shared__ float pr[C_][CTX_ + 1];

    const int n = blockIdx.x;
    const int h = blockIdx.y;
    const int tid = threadIdx.x;   // 0..127 == d

    // q scale: head_dim^-0.5 * log2(e) * softplus(per_dim_scale[d])
    const float qscale = 0.08838834764831845f * 1.4426950408889634f
                       * log1pf(expf(pds[tid]));

    // loads
#pragma unroll
    for (int c = 0; c < C_; c++) {
        int t = n * C_ + c;
        qs[c][tid] = (t < S_) ? q[(size_t)t * HD_ + h * D_ + tid] * qscale : 0.f;
    }
#pragma unroll
    for (int j = 0; j < CTX_; j++) {
        int p = n * C_ + j - MP_;
        bool ok = (p >= 0) && (p < S_);
        size_t off = (size_t)p * HD_ + h * D_ + tid;
        ks[j][tid] = ok ? k[off] : 0.f;
        vs[j][tid] = ok ? v[off] : 0.f;
    }
#pragma unroll
    for (int p = 0; p < POS_; p++)
        rks[p][tid] = relk[(size_t)p * HD_ + h * D_ + tid];
    __syncthreads();

    // content scores ac[c][j] = qs[c] . ks[j]
    for (int slot = tid; slot < C_ * CTX_; slot += 128) {
        int c = slot / CTX_, j = slot % CTX_;
        float s = 0.f;
#pragma unroll 16
        for (int d = 0; d < D_; d++) s = fmaf(qs[c][d], ks[j][d], s);
        ac[c][j] = s;
    }
    // rel-pos scores bd[c][p] = qs[c] . rks[p]
    for (int slot = tid; slot < C_ * POS_; slot += 128) {
        int c = slot / POS_, p = slot % POS_;
        float s = 0.f;
#pragma unroll 16
        for (int d = 0; d < D_; d++) s = fmaf(qs[c][d], rks[p][d], s);
        bd[c][p] = s;
    }
    __syncthreads();

    // rel-shift + softcap + softmax (one thread per query row)
    if (tid < C_) {
        const int c = tid;
        float sr[CTX_];
        float m = -1e30f;
#pragma unroll
        for (int j = 0; j < CTX_; j++) {
            int i  = c * CTX_ + j;
            int cp = i / (CTX_ + 1);
            int pp = i % (CTX_ + 1);
            float val = ac[c][j] + ((pp < POS_) ? bd[cp][pp] : 0.f);
            val = tanhf(val * 0.02f) * 50.f;
            sr[j] = val;
            m = fmaxf(m, val);
        }
        float sum = 0.f;
#pragma unroll
        for (int j = 0; j < CTX_; j++) { sr[j] = expf(sr[j] - m); sum += sr[j]; }
        float inv = 1.f / sum;
#pragma unroll
        for (int j = 0; j < CTX_; j++) pr[c][j] = sr[j] * inv;
    }
    __syncthreads();

    // out[c][d] = sum_j pr[c][j] * vs[j][d]
#pragma unroll
    for (int c = 0; c < C_; c++) {
        int t = n * C_ + c;
        if (t >= S_) break;
        float o = 0.f;
#pragma unroll
        for (int j = 0; j < CTX_; j++) o = fmaf(pr[c][j], vs[j][tid], o);
        ctx[(size_t)t * HD_ + h * D_ + tid] = o;
    }
}

// ---------------- launch ----------------
extern "C" void kernel_launch(void* const* d_in, const int* in_sizes, int n_in,
                              void* d_out, int out_size)
{
    const float* x     = (const float*)d_in[0];  // [1,S,HD]
    const float* pe    = (const float*)d_in[1];  // [POS,HD]
    const float* Wq    = (const float*)d_in[2];
    const float* Wk    = (const float*)d_in[3];
    const float* Wv    = (const float*)d_in[4];
    const float* Wrel  = (const float*)d_in[5];
    const float* Wpost = (const float*)d_in[6];
    const float* pds   = (const float*)d_in[7];  // [D]
    float* out = (float*)d_out;

    float *pq, *pk, *pv, *pctx, *prelk;
    cudaGetSymbolAddress((void**)&pq,    g_q);
    cudaGetSymbolAddress((void**)&pk,    g_k);
    cudaGetSymbolAddress((void**)&pv,    g_v);
    cudaGetSymbolAddress((void**)&pctx,  g_ctx);
    cudaGetSymbolAddress((void**)&prelk, g_relk);

    dim3 gbig(HD_ / 128, S_ / 128);   // (16, 64)
    dim3 grel(HD_ / 128, 1);

    sgemm128<<<gbig, 256>>>(x, Wq, pq, S_, HD_, HD_);
    sgemm128<<<gbig, 256>>>(x, Wk, pk, S_, HD_, HD_);
    sgemm128<<<gbig, 256>>>(x, Wv, pv, S_, HD_, HD_);
    sgemm128<<<grel, 256>>>(pe, Wrel, prelk, POS_, HD_, HD_);

    attn_kernel<<<dim3(NBLK_, H_), 128>>>(pq, pk, pv, prelk, pds, pctx);

    sgemm128<<<gbig, 256>>>(pctx, Wpost, out, S_, HD_, HD_);
}

// round 7
// speedup vs baseline: 2.7988x; 2.7988x over previous
#include <cuda_runtime.h>
#include <math.h>
#include <stdint.h>

// ---------------- problem constants ----------------
#define S_   8192
#define H_   16
#define D_   128
#define HD_  2048
#define C_   12
#define MP_  12
#define CTX_ 24
#define POS_ 13
#define NBLK_ 683          // ceil(8192/12)
#define KSPLIT_ 16

// scratch (device globals: allocation-free rule)
__device__ float g_q[(size_t)S_ * HD_];
__device__ float g_k[(size_t)S_ * HD_];
__device__ float g_v[(size_t)S_ * HD_];
__device__ float g_ctx[(size_t)S_ * HD_];
__device__ float g_xr[(size_t)S_ * HD_];
__device__ float g_wt0[(size_t)HD_ * HD_];
__device__ float g_wt1[(size_t)HD_ * HD_];
__device__ float g_wt2[(size_t)HD_ * HD_];
__device__ float g_wt3[(size_t)HD_ * HD_];
__device__ float g_relk[(size_t)POS_ * HD_];
__device__ float g_relpart[(size_t)KSPLIT_ * POS_ * HD_];

// ---------------- small PTX helpers ----------------
__device__ __forceinline__ uint32_t smem_u32(const void* p) {
    uint32_t a;
    asm("{ .reg .u64 t; cvta.to.shared.u64 t, %1; cvt.u32.u64 %0, t; }" : "=r"(a) : "l"(p));
    return a;
}
__device__ __forceinline__ float rtf32(float x) {
    uint32_t r;
    asm("cvt.rna.tf32.f32 %0, %1;" : "=r"(r) : "f"(x));
    return __uint_as_float(r);
}
__device__ __forceinline__ void cp_async16(uint32_t dst, const void* src) {
    asm volatile("cp.async.cg.shared.global [%0], [%1], 16;" :: "r"(dst), "l"(src) : "memory");
}
__device__ __forceinline__ void cp_commit() {
    asm volatile("cp.async.commit_group;" ::: "memory");
}
__device__ __forceinline__ void mma_tf32(float* d, const uint32_t* a, const uint32_t* b) {
    asm volatile("mma.sync.aligned.m16n8k8.row.col.f32.tf32.tf32.f32 "
                 "{%0,%1,%2,%3}, {%4,%5,%6,%7}, {%8,%9}, {%0,%1,%2,%3};"
                 : "+f"(d[0]), "+f"(d[1]), "+f"(d[2]), "+f"(d[3])
                 : "r"(a[0]), "r"(a[1]), "r"(a[2]), "r"(a[3]), "r"(b[0]), "r"(b[1]));
}

// ---------------- tf32 mma.sync GEMM ----------------
// C[M,2048] = A[M,2048] @ W[2048,2048]   (W row-major [K][N])
// CTA 128x128, BK=16, 3-stage cp.async, 8 warps (4 m x 2 n), warp tile 32x64.
#define BM_  128
#define BN_  128
#define BK_  16
#define NST_ 3
#define ASTR_ 20            // A smem row stride (floats), conflict-free
#define BSTR_ 136           // B smem row stride (floats), conflict-free
#define A_SZ_ (BM_ * ASTR_)             // 2560 floats
#define B_SZ_ (BK_ * BSTR_)             // 2176 floats
#define STG_SZ_ (A_SZ_ + B_SZ_)         // 4736 floats
#define GSMEM_ (NST_ * STG_SZ_ * 4)     // 56832 bytes
#define NIT_  (HD_ / BK_)               // 128

__global__ void __launch_bounds__(256, 1)
gemm_mma(const float* __restrict__ A, const float* __restrict__ W, float* __restrict__ C)
{
    extern __shared__ float smem[];
    const int tid  = threadIdx.x;
    const int warp = tid >> 5;
    const int lane = tid & 31;
    const int wm   = warp & 3;          // 0..3  -> m offset wm*32
    const int wn   = warp >> 2;         // 0..1  -> n offset wn*64
    const int brow = blockIdx.y * BM_;
    const int bcol = blockIdx.x * BN_;
    const int r    = lane >> 2;         // 0..7
    const int c    = lane & 3;          // 0..3

    // global load geometry
    const int arow  = tid >> 2;         // 0..63 (i=1 adds 64)
    const int acolv = (tid & 3) * 4;    // 0,4,8,12
    const int bkr   = tid >> 5;         // 0..7  (i=1 adds 8)
    const int bcolv = (tid & 31) * 4;   // 0..124

    const float* agp = A + (size_t)(brow + arow) * HD_ + acolv;
    const float* wgp = W + (size_t)bkr * HD_ + bcol + bcolv;
    const uint32_t sb = smem_u32(smem);

    float acc[2][8][4];
#pragma unroll
    for (int i = 0; i < 2; i++)
#pragma unroll
        for (int j = 0; j < 8; j++)
#pragma unroll
            for (int e = 0; e < 4; e++) acc[i][j][e] = 0.f;

    // prologue: fill NST_ stages
#pragma unroll
    for (int s = 0; s < NST_; s++) {
        const int k0 = s * BK_;
        uint32_t as = sb + (uint32_t)(s * STG_SZ_) * 4;
        uint32_t bs = as + A_SZ_ * 4;
#pragma unroll
        for (int i = 0; i < 2; i++)
            cp_async16(as + ((arow + i * 64) * ASTR_ + acolv) * 4,
                       agp + (size_t)(i * 64) * HD_ + k0);
#pragma unroll
        for (int i = 0; i < 2; i++)
            cp_async16(bs + ((bkr + i * 8) * BSTR_ + bcolv) * 4,
                       wgp + (size_t)(k0 + i * 8) * HD_);
        cp_commit();
    }

    for (int it = 0; it < NIT_; it++) {
        const int s = it % NST_;
        asm volatile("cp.async.wait_group 2;" ::: "memory");
        __syncthreads();

        const float* As = smem + s * STG_SZ_;
        const float* Bs = As + A_SZ_;

#pragma unroll
        for (int ks = 0; ks < 2; ks++) {
            const int kc = c + ks * 8;
            uint32_t af[2][4];
#pragma unroll
            for (int i = 0; i < 2; i++) {
                const int row = wm * 32 + i * 16 + r;
                af[i][0] = __float_as_uint(As[row * ASTR_ + kc]);
                af[i][1] = __float_as_uint(As[(row + 8) * ASTR_ + kc]);
                af[i][2] = __float_as_uint(As[row * ASTR_ + kc + 4]);
                af[i][3] = __float_as_uint(As[(row + 8) * ASTR_ + kc + 4]);
            }
            uint32_t bf[8][2];
#pragma unroll
            for (int j = 0; j < 8; j++) {
                const int n = wn * 64 + j * 8 + r;
                bf[j][0] = __float_as_uint(Bs[kc * BSTR_ + n]);
                bf[j][1] = __float_as_uint(Bs[(kc + 4) * BSTR_ + n]);
            }
#pragma unroll
            for (int i = 0; i < 2; i++)
#pragma unroll
                for (int j = 0; j < 8; j++)
                    mma_tf32(acc[i][j], af[i], bf[j]);
        }
        __syncthreads();

        if (it + NST_ < NIT_) {
            const int k0 = (it + NST_) * BK_;
            uint32_t as = sb + (uint32_t)(s * STG_SZ_) * 4;
            uint32_t bs = as + A_SZ_ * 4;
#pragma unroll
            for (int i = 0; i < 2; i++)
                cp_async16(as + ((arow + i * 64) * ASTR_ + acolv) * 4,
                           agp + (size_t)(i * 64) * HD_ + k0);
#pragma unroll
            for (int i = 0; i < 2; i++)
                cp_async16(bs + ((bkr + i * 8) * BSTR_ + bcolv) * 4,
                           wgp + (size_t)(k0 + i * 8) * HD_);
        }
        cp_commit();
    }

    // epilogue: direct global stores (float2, d-fragment layout)
#pragma unroll
    for (int i = 0; i < 2; i++) {
        const int row0 = brow + wm * 32 + i * 16 + r;
#pragma unroll
        for (int j = 0; j < 8; j++) {
            const int col = bcol + wn * 64 + j * 8 + c * 2;
            *(float2*)(C + (size_t)row0 * HD_ + col)       = make_float2(acc[i][j][0], acc[i][j][1]);
            *(float2*)(C + (size_t)(row0 + 8) * HD_ + col) = make_float2(acc[i][j][2], acc[i][j][3]);
        }
    }
}

// ---------------- tf32 rounding copy ----------------
__global__ void round_copy(const float* __restrict__ in, float* __restrict__ out, int n4)
{
    int i = blockIdx.x * blockDim.x + threadIdx.x;
    for (; i < n4; i += gridDim.x * blockDim.x) {
        float4 v = ((const float4*)in)[i];
        v.x = rtf32(v.x); v.y = rtf32(v.y); v.z = rtf32(v.z); v.w = rtf32(v.w);
        ((float4*)out)[i] = v;
    }
}

// ---------------- rel-position GEMM (split-K, exact fp32) ----------------
__global__ void relgemm_part(const float* __restrict__ pe, const float* __restrict__ W,
                             float* __restrict__ part)
{
    __shared__ float pes[POS_][128];
    const int tid = threadIdx.x;
    const int nb = blockIdx.x, ks = blockIdx.y;
    for (int idx = tid; idx < POS_ * 128; idx += 128) {
        int m = idx >> 7, kk = idx & 127;
        pes[m][kk] = pe[(size_t)m * HD_ + ks * 128 + kk];
    }
    __syncthreads();
    const int n = nb * 128 + tid;
    float acc[POS_];
#pragma unroll
    for (int m = 0; m < POS_; m++) acc[m] = 0.f;
    for (int kk = 0; kk < 128; kk++) {
        float w = W[(size_t)(ks * 128 + kk) * HD_ + n];
#pragma unroll
        for (int m = 0; m < POS_; m++) acc[m] = fmaf(pes[m][kk], w, acc[m]);
    }
#pragma unroll
    for (int m = 0; m < POS_; m++)
        part[((size_t)ks * POS_ + m) * HD_ + n] = acc[m];
}

__global__ void relgemm_reduce(const float* __restrict__ part, float* __restrict__ relk)
{
    int i = blockIdx.x * blockDim.x + threadIdx.x;
    if (i < POS_ * HD_) {
        float s = 0.f;
#pragma unroll
        for (int ks = 0; ks < KSPLIT_; ks++) s += part[(size_t)ks * POS_ * HD_ + i];
        relk[i] = s;
    }
}

// ---------------- chunked attention: one block per (n, h) ----------------
__global__ __launch_bounds__(128)
void attn_kernel(const float* __restrict__ q, const float* __restrict__ k,
                 const float* __restrict__ v, const float* __restrict__ relk,
                 const float* __restrict__ pds, float* __restrict__ ctx)
{
    __shared__ float qs[C_][D_ + 1];
    __shared__ float ks[CTX_][D_ + 1];
    __shared__ float vs[CTX_][D_ + 1];
    __shared__ float rks[POS_][D_ + 1];
    __shared__ float ac[C_][CTX_ + 1];
    __shared__ float bd[C_][POS_ + 1];
    __shared__ float pr[C_][CTX_ + 1];

    const int n = blockIdx.x;
    const int h = blockIdx.y;
    const int tid = threadIdx.x;   // 0..127 == d

    const float qscale = 0.08838834764831845f * 1.4426950408889634f
                       * log1pf(expf(pds[tid]));

#pragma unroll
    for (int c = 0; c < C_; c++) {
        int t = n * C_ + c;
        qs[c][tid] = (t < S_) ? q[(size_t)t * HD_ + h * D_ + tid] * qscale : 0.f;
    }
#pragma unroll
    for (int j = 0; j < CTX_; j++) {
        int p = n * C_ + j - MP_;
        bool ok = (p >= 0) && (p < S_);
        size_t off = (size_t)p * HD_ + h * D_ + tid;
        ks[j][tid] = ok ? k[off] : 0.f;
        vs[j][tid] = ok ? v[off] : 0.f;
    }
#pragma unroll
    for (int p = 0; p < POS_; p++)
        rks[p][tid] = relk[(size_t)p * HD_ + h * D_ + tid];
    __syncthreads();

    for (int slot = tid; slot < C_ * CTX_; slot += 128) {
        int c = slot / CTX_, j = slot % CTX_;
        float s = 0.f;
#pragma unroll 16
        for (int d = 0; d < D_; d++) s = fmaf(qs[c][d], ks[j][d], s);
        ac[c][j] = s;
    }
    for (int slot = tid; slot < C_ * POS_; slot += 128) {
        int c = slot / POS_, p = slot % POS_;
        float s = 0.f;
#pragma unroll 16
        for (int d = 0; d < D_; d++) s = fmaf(qs[c][d], rks[p][d], s);
        bd[c][p] = s;
    }
    __syncthreads();

    if (tid < C_) {
        const int c = tid;
        float sr[CTX_];
        float m = -1e30f;
#pragma unroll
        for (int j = 0; j < CTX_; j++) {
            int i  = c * CTX_ + j;
            int cp = i / (CTX_ + 1);
            int pp = i % (CTX_ + 1);
            float val = ac[c][j] + ((pp < POS_) ? bd[cp][pp] : 0.f);
            val = tanhf(val * 0.02f) * 50.f;
            sr[j] = val;
            m = fmaxf(m, val);
        }
        float sum = 0.f;
#pragma unroll
        for (int j = 0; j < CTX_; j++) { sr[j] = expf(sr[j] - m); sum += sr[j]; }
        float inv = 1.f / sum;
#pragma unroll
        for (int j = 0; j < CTX_; j++) pr[c][j] = sr[j] * inv;
    }
    __syncthreads();

#pragma unroll
    for (int c = 0; c < C_; c++) {
        int t = n * C_ + c;
        if (t >= S_) break;
        float o = 0.f;
#pragma unroll
        for (int j = 0; j < CTX_; j++) o = fmaf(pr[c][j], vs[j][tid], o);
        ctx[(size_t)t * HD_ + h * D_ + tid] = rtf32(o);   // pre-round for tf32 post-GEMM
    }
}

// ---------------- launch ----------------
extern "C" void kernel_launch(void* const* d_in, const int* in_sizes, int n_in,
                              void* d_out, int out_size)
{
    const float* x     = (const float*)d_in[0];
    const float* pe    = (const float*)d_in[1];
    const float* Wq    = (const float*)d_in[2];
    const float* Wk    = (const float*)d_in[3];
    const float* Wv    = (const float*)d_in[4];
    const float* Wrel  = (const float*)d_in[5];
    const float* Wpost = (const float*)d_in[6];
    const float* pds   = (const float*)d_in[7];
    float* out = (float*)d_out;

    float *pq, *pk, *pv, *pctx, *pxr, *pw0, *pw1, *pw2, *pw3, *prelk, *ppart;
    cudaGetSymbolAddress((void**)&pq,    g_q);
    cudaGetSymbolAddress((void**)&pk,    g_k);
    cudaGetSymbolAddress((void**)&pv,    g_v);
    cudaGetSymbolAddress((void**)&pctx,  g_ctx);
    cudaGetSymbolAddress((void**)&pxr,   g_xr);
    cudaGetSymbolAddress((void**)&pw0,   g_wt0);
    cudaGetSymbolAddress((void**)&pw1,   g_wt1);
    cudaGetSymbolAddress((void**)&pw2,   g_wt2);
    cudaGetSymbolAddress((void**)&pw3,   g_wt3);
    cudaGetSymbolAddress((void**)&prelk, g_relk);
    cudaGetSymbolAddress((void**)&ppart, g_relpart);

    cudaFuncSetAttribute(gemm_mma, cudaFuncAttributeMaxDynamicSharedMemorySize, GSMEM_);

    // prep: tf32-round X and weights (W stays [K][N]; no transpose needed)
    round_copy<<<4096, 256>>>(x,     pxr, S_ * HD_ / 4);
    round_copy<<<2048, 256>>>(Wq,    pw0, HD_ * HD_ / 4);
    round_copy<<<2048, 256>>>(Wk,    pw1, HD_ * HD_ / 4);
    round_copy<<<2048, 256>>>(Wv,    pw2, HD_ * HD_ / 4);
    round_copy<<<2048, 256>>>(Wpost, pw3, HD_ * HD_ / 4);

    // big GEMMs on tensor cores (legacy mma.sync path)
    dim3 gg(HD_ / BN_, S_ / BM_);   // (16, 64)
    gemm_mma<<<gg, 256, GSMEM_>>>(pxr, pw0, pq);
    gemm_mma<<<gg, 256, GSMEM_>>>(pxr, pw1, pk);
    gemm_mma<<<gg, 256, GSMEM_>>>(pxr, pw2, pv);

    // rel-position GEMM (tiny, split-K, exact fp32)
    relgemm_part<<<dim3(HD_ / 128, KSPLIT_), 128>>>(pe, Wrel, ppart);
    relgemm_reduce<<<(POS_ * HD_ + 255) / 256, 256>>>(ppart, prelk);

    attn_kernel<<<dim3(NBLK_, H_), 128>>>(pq, pk, pv, prelk, pds, pctx);

    gemm_mma<<<gg, 256, GSMEM_>>>(pctx, pw3, out);
}

// round 8
// speedup vs baseline: 3.9051x; 1.3953x over previous
#include <cuda_runtime.h>
#include <math.h>
#include <stdint.h>

// ---------------- problem constants ----------------
#define S_   8192
#define H_   16
#define D_   128
#define HD_  2048
#define C_   12
#define MP_  12
#define CTX_ 24
#define POS_ 13
#define NBLK_ 683          // ceil(8192/12)
#define KSPLIT_ 16

// scratch (device globals: allocation-free rule)
__device__ float g_q[(size_t)S_ * HD_];
__device__ float g_k[(size_t)S_ * HD_];
__device__ float g_v[(size_t)S_ * HD_];
__device__ float g_ctx[(size_t)S_ * HD_];
__device__ float g_xr[(size_t)S_ * HD_];
__device__ float g_wt0[(size_t)HD_ * HD_];
__device__ float g_wt1[(size_t)HD_ * HD_];
__device__ float g_wt2[(size_t)HD_ * HD_];
__device__ float g_wt3[(size_t)HD_ * HD_];
__device__ float g_relk[(size_t)POS_ * HD_];
__device__ float g_relpart[(size_t)KSPLIT_ * POS_ * HD_];

// ---------------- small PTX helpers ----------------
__device__ __forceinline__ uint32_t smem_u32(const void* p) {
    uint32_t a;
    asm("{ .reg .u64 t; cvta.to.shared.u64 t, %1; cvt.u32.u64 %0, t; }" : "=r"(a) : "l"(p));
    return a;
}
__device__ __forceinline__ float rtf32(float x) {
    uint32_t r;
    asm("cvt.rna.tf32.f32 %0, %1;" : "=r"(r) : "f"(x));
    return __uint_as_float(r);
}
__device__ __forceinline__ void cp_async16(uint32_t dst, const void* src) {
    asm volatile("cp.async.cg.shared.global [%0], [%1], 16;" :: "r"(dst), "l"(src) : "memory");
}
__device__ __forceinline__ void cp_commit() {
    asm volatile("cp.async.commit_group;" ::: "memory");
}
__device__ __forceinline__ void mma_tf32(float* d, const uint32_t* a, const uint32_t* b) {
    asm volatile("mma.sync.aligned.m16n8k8.row.col.f32.tf32.tf32.f32 "
                 "{%0,%1,%2,%3}, {%4,%5,%6,%7}, {%8,%9}, {%0,%1,%2,%3};"
                 : "+f"(d[0]), "+f"(d[1]), "+f"(d[2]), "+f"(d[3])
                 : "r"(a[0]), "r"(a[1]), "r"(a[2]), "r"(a[3]), "r"(b[0]), "r"(b[1]));
}

// ---------------- tf32 mma.sync GEMM ----------------
// C[M,2048] = A[M,2048] @ W[2048,2048]   (W row-major [K][N])
// CTA 128x128, BK=16, 4-stage cp.async, 8 warps (4 m x 2 n), warp tile 32x64.
// Single __syncthreads per k-iter; refill issued before compute; 2 CTAs/SM.
#define BM_  128
#define BN_  128
#define BK_  16
#define NST_ 4
#define ASTR_ 20            // A smem row stride (floats), conflict-free
#define BSTR_ 136           // B smem row stride (floats), conflict-free
#define A_SZ_ (BM_ * ASTR_)             // 2560 floats
#define B_SZ_ (BK_ * BSTR_)             // 2176 floats
#define STG_SZ_ (A_SZ_ + B_SZ_)         // 4736 floats
#define GSMEM_ (NST_ * STG_SZ_ * 4)     // 75776 bytes
#define NIT_  (HD_ / BK_)               // 128

struct GemmBody {
    const float* agp;
    const float* wgp;
    uint32_t sb;
    int arow, acolv, bkr, bcolv;

    __device__ __forceinline__ void stage_load(int s, int k0) const {
        uint32_t as = sb + (uint32_t)(s * STG_SZ_) * 4;
        uint32_t bs = as + A_SZ_ * 4;
#pragma unroll
        for (int i = 0; i < 2; i++)
            cp_async16(as + ((arow + i * 64) * ASTR_ + acolv) * 4,
                       agp + (size_t)(i * 64) * HD_ + k0);
#pragma unroll
        for (int i = 0; i < 2; i++)
            cp_async16(bs + ((bkr + i * 8) * BSTR_ + bcolv) * 4,
                       wgp + (size_t)(k0 + i * 8) * HD_);
    }
};

__global__ void __launch_bounds__(256, 2)
gemm_mma_qkv(const float* __restrict__ A,
             const float* __restrict__ W0, const float* __restrict__ W1,
             const float* __restrict__ W2,
             float* __restrict__ C0, float* __restrict__ C1, float* __restrict__ C2)
{
    extern __shared__ float smem[];
    const int tid  = threadIdx.x;
    const int warp = tid >> 5;
    const int lane = tid & 31;
    const int wm   = warp & 3;          // m offset wm*32
    const int wn   = warp >> 2;         // n offset wn*64
    const int brow = blockIdx.y * BM_;
    const int bcol = blockIdx.x * BN_;
    const int r    = lane >> 2;         // 0..7
    const int c    = lane & 3;          // 0..3

    const float* W = (blockIdx.z == 0) ? W0 : (blockIdx.z == 1) ? W1 : W2;
    float* Cc      = (blockIdx.z == 0) ? C0 : (blockIdx.z == 1) ? C1 : C2;

    GemmBody gb;
    gb.arow  = tid >> 2;
    gb.acolv = (tid & 3) * 4;
    gb.bkr   = tid >> 5;
    gb.bcolv = (tid & 31) * 4;
    gb.agp = A + (size_t)(brow + gb.arow) * HD_ + gb.acolv;
    gb.wgp = W + (size_t)gb.bkr * HD_ + bcol + gb.bcolv;
    gb.sb  = smem_u32(smem);

    float acc[2][8][4];
#pragma unroll
    for (int i = 0; i < 2; i++)
#pragma unroll
        for (int j = 0; j < 8; j++)
#pragma unroll
            for (int e = 0; e < 4; e++) acc[i][j][e] = 0.f;

    // prologue: stages 0..NST-2
#pragma unroll
    for (int s = 0; s < NST_ - 1; s++) {
        gb.stage_load(s, s * BK_);
        cp_commit();
    }

    for (int it = 0; it < NIT_; it++) {
        const int s = it & (NST_ - 1);
        asm volatile("cp.async.wait_group %0;" :: "n"(NST_ - 2) : "memory");
        __syncthreads();
        // barrier proves: stage s loaded; all warps done reading stage (it+3)%4
        // (read at iter it-1) -> safe to overwrite it now.
        if (it + NST_ - 1 < NIT_)
            gb.stage_load((it + NST_ - 1) & (NST_ - 1), (it + NST_ - 1) * BK_);
        cp_commit();

        const float* As = smem + s * STG_SZ_;
        const float* Bs = As + A_SZ_;

#pragma unroll
        for (int ks = 0; ks < 2; ks++) {
            const int kc = c + ks * 8;
            uint32_t af[2][4];
#pragma unroll
            for (int i = 0; i < 2; i++) {
                const int row = wm * 32 + i * 16 + r;
                af[i][0] = __float_as_uint(As[row * ASTR_ + kc]);
                af[i][1] = __float_as_uint(As[(row + 8) * ASTR_ + kc]);
                af[i][2] = __float_as_uint(As[row * ASTR_ + kc + 4]);
                af[i][3] = __float_as_uint(As[(row + 8) * ASTR_ + kc + 4]);
            }
            uint32_t bf[8][2];
#pragma unroll
            for (int j = 0; j < 8; j++) {
                const int n = wn * 64 + j * 8 + r;
                bf[j][0] = __float_as_uint(Bs[kc * BSTR_ + n]);
                bf[j][1] = __float_as_uint(Bs[(kc + 4) * BSTR_ + n]);
            }
#pragma unroll
            for (int i = 0; i < 2; i++)
#pragma unroll
                for (int j = 0; j < 8; j++)
                    mma_tf32(acc[i][j], af[i], bf[j]);
        }
    }

    // epilogue: direct global stores (float2, d-fragment layout)
#pragma unroll
    for (int i = 0; i < 2; i++) {
        const int row0 = brow + wm * 32 + i * 16 + r;
#pragma unroll
        for (int j = 0; j < 8; j++) {
            const int col = bcol + wn * 64 + j * 8 + c * 2;
            *(float2*)(Cc + (size_t)row0 * HD_ + col)       = make_float2(acc[i][j][0], acc[i][j][1]);
            *(float2*)(Cc + (size_t)(row0 + 8) * HD_ + col) = make_float2(acc[i][j][2], acc[i][j][3]);
        }
    }
}

// ---------------- tf32 rounding copy ----------------
__global__ void round_copy(const float* __restrict__ in, float* __restrict__ out, int n4)
{
    int i = blockIdx.x * blockDim.x + threadIdx.x;
    for (; i < n4; i += gridDim.x * blockDim.x) {
        float4 v = ((const float4*)in)[i];
        v.x = rtf32(v.x); v.y = rtf32(v.y); v.z = rtf32(v.z); v.w = rtf32(v.w);
        ((float4*)out)[i] = v;
    }
}

// ---------------- rel-position GEMM (split-K, exact fp32) ----------------
__global__ void relgemm_part(const float* __restrict__ pe, const float* __restrict__ W,
                             float* __restrict__ part)
{
    __shared__ float pes[POS_][128];
    const int tid = threadIdx.x;
    const int nb = blockIdx.x, ks = blockIdx.y;
    for (int idx = tid; idx < POS_ * 128; idx += 128) {
        int m = idx >> 7, kk = idx & 127;
        pes[m][kk] = pe[(size_t)m * HD_ + ks * 128 + kk];
    }
    __syncthreads();
    const int n = nb * 128 + tid;
    float acc[POS_];
#pragma unroll
    for (int m = 0; m < POS_; m++) acc[m] = 0.f;
    for (int kk = 0; kk < 128; kk++) {
        float w = W[(size_t)(ks * 128 + kk) * HD_ + n];
#pragma unroll
        for (int m = 0; m < POS_; m++) acc[m] = fmaf(pes[m][kk], w, acc[m]);
    }
#pragma unroll
    for (int m = 0; m < POS_; m++)
        part[((size_t)ks * POS_ + m) * HD_ + n] = acc[m];
}

__global__ void relgemm_reduce(const float* __restrict__ part, float* __restrict__ relk)
{
    int i = blockIdx.x * blockDim.x + threadIdx.x;
    if (i < POS_ * HD_) {
        float s = 0.f;
#pragma unroll
        for (int ks = 0; ks < KSPLIT_; ks++) s += part[(size_t)ks * POS_ * HD_ + i];
        relk[i] = s;
    }
}

// ---------------- chunked attention: one block per (n, h) ----------------
__global__ __launch_bounds__(128)
void attn_kernel(const float* __restrict__ q, const float* __restrict__ k,
                 const float* __restrict__ v, const float* __restrict__ relk,
                 const float* __restrict__ pds, float* __restrict__ ctx)
{
    __shared__ float qs[C_][D_ + 1];
    __shared__ float ks[CTX_][D_ + 1];
    __shared__ float vs[CTX_][D_ + 1];
    __shared__ float rks[POS_][D_ + 1];
    __shared__ float ac[C_][CTX_ + 1];
    __shared__ float bd[C_][POS_ + 1];
    __shared__ float pr[C_][CTX_ + 1];

    const int n = blockIdx.x;
    const int h = blockIdx.y;
    const int tid = threadIdx.x;   // 0..127 == d

    const float qscale = 0.08838834764831845f * 1.4426950408889634f
                       * log1pf(expf(pds[tid]));

#pragma unroll
    for (int c = 0; c < C_; c++) {
        int t = n * C_ + c;
        qs[c][tid] = (t < S_) ? q[(size_t)t * HD_ + h * D_ + tid] * qscale : 0.f;
    }
#pragma unroll
    for (int j = 0; j < CTX_; j++) {
        int p = n * C_ + j - MP_;
        bool ok = (p >= 0) && (p < S_);
        size_t off = (size_t)p * HD_ + h * D_ + tid;
        ks[j][tid] = ok ? k[off] : 0.f;
        vs[j][tid] = ok ? v[off] : 0.f;
    }
#pragma unroll
    for (int p = 0; p < POS_; p++)
        rks[p][tid] = relk[(size_t)p * HD_ + h * D_ + tid];
    __syncthreads();

    for (int slot = tid; slot < C_ * CTX_; slot += 128) {
        int c = slot / CTX_, j = slot % CTX_;
        float s = 0.f;
#pragma unroll 16
        for (int d = 0; d < D_; d++) s = fmaf(qs[c][d], ks[j][d], s);
        ac[c][j] = s;
    }
    for (int slot = tid; slot < C_ * POS_; slot += 128) {
        int c = slot / POS_, p = slot % POS_;
        float s = 0.f;
#pragma unroll 16
        for (int d = 0; d < D_; d++) s = fmaf(qs[c][d], rks[p][d], s);
        bd[c][p] = s;
    }
    __syncthreads();

    if (tid < C_) {
        const int c = tid;
        float sr[CTX_];
        float m = -1e30f;
#pragma unroll
        for (int j = 0; j < CTX_; j++) {
            int i  = c * CTX_ + j;
            int cp = i / (CTX_ + 1);
            int pp = i % (CTX_ + 1);
            float val = ac[c][j] + ((pp < POS_) ? bd[cp][pp] : 0.f);
            val = tanhf(val * 0.02f) * 50.f;
            sr[j] = val;
            m = fmaxf(m, val);
        }
        float sum = 0.f;
#pragma unroll
        for (int j = 0; j < CTX_; j++) { sr[j] = expf(sr[j] - m); sum += sr[j]; }
        float inv = 1.f / sum;
#pragma unroll
        for (int j = 0; j < CTX_; j++) pr[c][j] = sr[j] * inv;
    }
    __syncthreads();

#pragma unroll
    for (int c = 0; c < C_; c++) {
        int t = n * C_ + c;
        if (t >= S_) break;
        float o = 0.f;
#pragma unroll
        for (int j = 0; j < CTX_; j++) o = fmaf(pr[c][j], vs[j][tid], o);
        ctx[(size_t)t * HD_ + h * D_ + tid] = rtf32(o);   // pre-round for tf32 post-GEMM
    }
}

// ---------------- launch ----------------
extern "C" void kernel_launch(void* const* d_in, const int* in_sizes, int n_in,
                              void* d_out, int out_size)
{
    const float* x     = (const float*)d_in[0];
    const float* pe    = (const float*)d_in[1];
    const float* Wq    = (const float*)d_in[2];
    const float* Wk    = (const float*)d_in[3];
    const float* Wv    = (const float*)d_in[4];
    const float* Wrel  = (const float*)d_in[5];
    const float* Wpost = (const float*)d_in[6];
    const float* pds   = (const float*)d_in[7];
    float* out = (float*)d_out;

    float *pq, *pk, *pv, *pctx, *pxr, *pw0, *pw1, *pw2, *pw3, *prelk, *ppart;
    cudaGetSymbolAddress((void**)&pq,    g_q);
    cudaGetSymbolAddress((void**)&pk,    g_k);
    cudaGetSymbolAddress((void**)&pv,    g_v);
    cudaGetSymbolAddress((void**)&pctx,  g_ctx);
    cudaGetSymbolAddress((void**)&pxr,   g_xr);
    cudaGetSymbolAddress((void**)&pw0,   g_wt0);
    cudaGetSymbolAddress((void**)&pw1,   g_wt1);
    cudaGetSymbolAddress((void**)&pw2,   g_wt2);
    cudaGetSymbolAddress((void**)&pw3,   g_wt3);
    cudaGetSymbolAddress((void**)&prelk, g_relk);
    cudaGetSymbolAddress((void**)&ppart, g_relpart);

    cudaFuncSetAttribute(gemm_mma_qkv, cudaFuncAttributeMaxDynamicSharedMemorySize, GSMEM_);

    // prep: tf32-round X and weights (W stays [K][N]; no transpose needed)
    round_copy<<<4096, 256>>>(x,     pxr, S_ * HD_ / 4);
    round_copy<<<2048, 256>>>(Wq,    pw0, HD_ * HD_ / 4);
    round_copy<<<2048, 256>>>(Wk,    pw1, HD_ * HD_ / 4);
    round_copy<<<2048, 256>>>(Wv,    pw2, HD_ * HD_ / 4);
    round_copy<<<2048, 256>>>(Wpost, pw3, HD_ * HD_ / 4);

    // fused QKV GEMM on tensor cores (grid.z selects weight/output)
    dim3 gq(HD_ / BN_, S_ / BM_, 3);   // (16, 64, 3)
    gemm_mma_qkv<<<gq, 256, GSMEM_>>>(pxr, pw0, pw1, pw2, pq, pk, pv);

    // rel-position GEMM (tiny, split-K, exact fp32)
    relgemm_part<<<dim3(HD_ / 128, KSPLIT_), 128>>>(pe, Wrel, ppart);
    relgemm_reduce<<<(POS_ * HD_ + 255) / 256, 256>>>(ppart, prelk);

    attn_kernel<<<dim3(NBLK_, H_), 128>>>(pq, pk, pv, prelk, pds, pctx);

    // post GEMM (reuse same kernel; all three W slots point to Wpost, write out)
    dim3 gp(HD_ / BN_, S_ / BM_, 1);
    gemm_mma_qkv<<<gp, 256, GSMEM_>>>(pctx, pw3, pw3, pw3, out, out, out);
}